// round 12
// baseline (speedup 1.0000x reference)
#include <cuda_runtime.h>
#include <math.h>

#define B       16
#define N       128
#define NC      80
#define HW0     25600
#define HW1     6400
#define HW2     1600
#define CHUNK   800                  // MUST stay <= 1024 (10-bit local idx)
#define CH0     (HW0 / CHUNK)        // 32
#define CH1     (HW1 / CHUNK)        // 8
#define CH2     (HW2 / CHUNK)        // 2
#define NCHUNKS (CH0 + CH1 + CH2)    // 42
#define NGRP    (3 * B * 2)          // 96 (lvl, b, gh) gather groups

// Scratch (no device allocations allowed). All tickets self-reset each run.
__device__ unsigned long long g_part[B][N][NCHUNKS];  // argmin partials (transposed: keys contiguous per (b,g))
__device__ float        g_blk[3][NGRP];               // per-group loss partials
__device__ unsigned int g_tick[3][B][2];              // per-(lvl,b,gh) chunk-completion tickets
__device__ unsigned int g_count;                      // final ticket over 96 groups

// Packed f32x2 ops (sm_103a; ptxas won't auto-fuse -- must be PTX)
#define PACK_F32X2(out, lo, hi) \
    asm("mov.b64 %0, {%1, %2};" : "=l"(out) : "f"(lo), "f"(hi))
#define UNPACK_U32X2(lo, hi, in) \
    asm("mov.b64 {%0, %1}, %2;" : "=r"(lo), "=r"(hi) : "l"(in))
#define ADD_F32X2(out, a, b) \
    asm("add.rn.f32x2 %0, %1, %2;" : "=l"(out) : "l"(a), "l"(b))
#define MUL_F32X2(out, a, b) \
    asm("mul.rn.f32x2 %0, %1, %2;" : "=l"(out) : "l"(a), "l"(b))
#define FMA_F32X2(out, a, b, c) \
    asm("fma.rn.f32x2 %0, %1, %2, %3;" : "=l"(out) : "l"(a), "l"(b), "l"(c))

// ---------------------------------------------------------------------------
// SINGLE fused kernel.
// Phase A (all 1344 blocks): R8 argmin inner loop, verbatim. Grid
// (NCHUNKS, B, 2); block 256 = 32 lanes x 8 warps; 8 gts/thread.
// Phase B (96 blocks -- the LAST chunk-block to finish per (lvl,b,gh)):
// gather + CE/L1 for that group's 64 tuples, 2 tuples interleaved per warp
// (proven MLP win). Runs overlapped with remaining Phase-A blocks.
// Phase C (1 block -- last of the 96 groups): deterministic 96-way final
// reduction, writes the 3 outputs, resets the final ticket.
// Ticket order never affects values (fixed-order summation) -> deterministic.
// ---------------------------------------------------------------------------
__global__ __launch_bounds__(256)
void fused_kernel(const float* __restrict__ cls0,
                  const float* __restrict__ cls1,
                  const float* __restrict__ cls2,
                  const float* __restrict__ reg0,
                  const float* __restrict__ reg1,
                  const float* __restrict__ reg2,
                  const float* __restrict__ gt,
                  const int*   __restrict__ labels,
                  float*       __restrict__ out) {
    const int bx = blockIdx.x;   // chunk slot 0..41
    const int b  = blockIdx.y;
    const int gh = blockIdx.z;   // gt half

    int lvl, chunk, HW, nch;
    const float* reg;
    if (bx < CH0)            { lvl = 0; chunk = bx;               HW = HW0; reg = reg0; nch = CH0; }
    else if (bx < CH0 + CH1) { lvl = 1; chunk = bx - CH0;         HW = HW1; reg = reg1; nch = CH1; }
    else                     { lvl = 2; chunk = bx - (CH0 + CH1); HW = HW2; reg = reg2; nch = CH2; }

    const int tx = threadIdx.x & 31;
    const int ty = threadIdx.x >> 5;           // 0..7
    const int gbase = gh * 64 + ty * 8;        // first of this thread's 8 gts

    // ---------------- Phase A: argmin (R8 form, verbatim) ----------------
    unsigned long long gnx[4], gny[4];
    unsigned kmin[8];
    const float* gtb = gt + ((size_t)b * N + gbase) * 4;
#pragma unroll
    for (int j = 0; j < 4; j++) {
        float a0 = -gtb[(2 * j    ) * 4 + 0];
        float a1 = -gtb[(2 * j + 1) * 4 + 0];
        float b0 = -gtb[(2 * j    ) * 4 + 1];
        float b1 = -gtb[(2 * j + 1) * 4 + 1];
        PACK_F32X2(gnx[j], a0, a1);
        PACK_F32X2(gny[j], b0, b1);
    }
#pragma unroll
    for (int i = 0; i < 8; i++) kmin[i] = 0xFFFFFFFFu;

    const float* regb = reg + (size_t)b * HW * 4;
    const int pbase = chunk * CHUNK;
    const int pend  = pbase + CHUNK;

    unsigned plocal = tx;
#pragma unroll 5
    for (int p = pbase + tx; p < pend; p += 32, plocal += 32) {
        float4 v = *reinterpret_cast<const float4*>(regb + (size_t)p * 4);
        unsigned long long pxx, pyy;
        PACK_F32X2(pxx, v.x, v.x);
        PACK_F32X2(pyy, v.y, v.y);
#pragma unroll
        for (int j = 0; j < 4; j++) {
            unsigned long long dx2, dy2, m, d2v;
            ADD_F32X2(dx2, gnx[j], pxx);     // (px-gx, px-gx')
            ADD_F32X2(dy2, gny[j], pyy);
            MUL_F32X2(m, dx2, dx2);
            FMA_F32X2(d2v, dy2, dy2, m);
            unsigned lo, hi;
            UNPACK_U32X2(lo, hi, d2v);
            unsigned k0 = (lo & 0xFFFFFC00u) | plocal;   // LOP3
            unsigned k1 = (hi & 0xFFFFFC00u) | plocal;
            kmin[2 * j]     = umin(kmin[2 * j],     k0); // IMNMX
            kmin[2 * j + 1] = umin(kmin[2 * j + 1], k1);
        }
    }

#pragma unroll
    for (int i = 0; i < 8; i++) {
        unsigned k = kmin[i];
#pragma unroll
        for (int off = 16; off > 0; off >>= 1)
            k = umin(k, __shfl_xor_sync(0xFFFFFFFFu, k, off));
        if (tx == 0) {
            unsigned idx = (unsigned)pbase + (k & 0x3FFu);
            g_part[b][gbase + i][bx] =
                ((unsigned long long)(k & 0xFFFFFC00u) << 32) | idx;
        }
    }

    // ---------------- Ticket: last chunk-block of (lvl,b,gh) gathers -------
    __shared__ int s_flag;
    __syncthreads();
    if (threadIdx.x == 0) {
        __threadfence();
        unsigned t = atomicAdd(&g_tick[lvl][b][gh], 1u);
        int last = (t == (unsigned)(nch - 1));
        s_flag = last;
        if (last) g_tick[lvl][b][gh] = 0;   // all nch arrived; safe self-reset
    }
    __syncthreads();
    if (!s_flag) return;
    __threadfence();   // make other blocks' g_part writes visible

    // ---------------- Phase B: gather + CE/L1 for this group's 64 tuples --
    const float* cls = (lvl == 0) ? cls0 : (lvl == 1) ? cls1 : cls2;
    const int s0 = (lvl == 0) ? 0 : (lvl == 1) ? CH0 : (CH0 + CH1);
    const float NEGINF = -__int_as_float(0x7F800000);

    float acc_ce = 0.0f, acc_l1 = 0.0f, acc_w = 0.0f;   // lane-0 accumulators

#pragma unroll
    for (int pr = 0; pr < 4; pr++) {
        const int gA = gbase + pr * 2;
        const int gB = gA + 1;

        unsigned long long keyA = 0xFFFFFFFFFFFFFFFFULL;
        unsigned long long keyB = 0xFFFFFFFFFFFFFFFFULL;
        if (tx < nch) {
            keyA = g_part[b][gA][s0 + tx];
            keyB = g_part[b][gB][s0 + tx];
        }
#pragma unroll
        for (int off = 16; off > 0; off >>= 1) {
            unsigned long long a2 = __shfl_xor_sync(0xFFFFFFFFu, keyA, off);
            unsigned long long b2 = __shfl_xor_sync(0xFFFFFFFFu, keyB, off);
            keyA = (a2 < keyA) ? a2 : keyA;
            keyB = (b2 < keyB) ? b2 : keyB;
        }
        const unsigned idA = (unsigned)keyA;
        const unsigned idB = (unsigned)keyB;

        // Issue all dependent scalar loads now; consume after reductions.
        const float* crowA = cls + ((size_t)b * HW + idA) * NC;
        const float* crowB = cls + ((size_t)b * HW + idB) * NC;
        float4 gA4 = *reinterpret_cast<const float4*>(gt + ((size_t)b * N + gA) * 4);
        float4 gB4 = *reinterpret_cast<const float4*>(gt + ((size_t)b * N + gB) * 4);
        float4 rA4 = *reinterpret_cast<const float4*>(reg + ((size_t)b * HW + idA) * 4);
        float4 rB4 = *reinterpret_cast<const float4*>(reg + ((size_t)b * HW + idB) * 4);
        float logitA = crowA[labels[b * N + gA]];
        float logitB = crowB[labels[b * N + gB]];

        float a0 = NEGINF, a1 = NEGINF, a2v = NEGINF;
        float c0 = NEGINF, c1 = NEGINF, c2v = NEGINF;
        if (tx < NC)      { a0  = crowA[tx];      c0  = crowB[tx]; }
        if (tx + 32 < NC) { a1  = crowA[tx + 32]; c1  = crowB[tx + 32]; }
        if (tx + 64 < NC) { a2v = crowA[tx + 64]; c2v = crowB[tx + 64]; }
        float mxA = fmaxf(a0, fmaxf(a1, a2v));
        float mxB = fmaxf(c0, fmaxf(c1, c2v));
#pragma unroll
        for (int off = 16; off > 0; off >>= 1) {
            mxA = fmaxf(mxA, __shfl_xor_sync(0xFFFFFFFFu, mxA, off));
            mxB = fmaxf(mxB, __shfl_xor_sync(0xFFFFFFFFu, mxB, off));
        }
        float smA = 0.0f, smB = 0.0f;
        if (tx < NC)      { smA += expf(a0  - mxA); smB += expf(c0  - mxB); }
        if (tx + 32 < NC) { smA += expf(a1  - mxA); smB += expf(c1  - mxB); }
        if (tx + 64 < NC) { smA += expf(a2v - mxA); smB += expf(c2v - mxB); }
#pragma unroll
        for (int off = 16; off > 0; off >>= 1) {
            smA += __shfl_xor_sync(0xFFFFFFFFu, smA, off);
            smB += __shfl_xor_sync(0xFFFFFFFFu, smB, off);
        }
        if (tx == 0) {
            float lseA = mxA + logf(smA);
            float lseB = mxB + logf(smB);

            float dxA = gA4.x - rA4.x, dyA = gA4.y - rA4.y;
            float dxB = gB4.x - rB4.x, dyB = gB4.y - rB4.y;
            float d2A = dxA * dxA + dyA * dyA;
            float d2B = dxB * dxB + dyB * dyB;
            float wA = (sqrtf(d2A) < 2.5f) ? 1.0f : 0.0f;
            float wB = (sqrtf(d2B) < 2.5f) ? 1.0f : 0.0f;

            float l1A = fabsf(rA4.x - gA4.x) + fabsf(rA4.y - gA4.y) +
                        fabsf(rA4.z - gA4.z) + fabsf(rA4.w - gA4.w);
            float l1B = fabsf(rB4.x - gB4.x) + fabsf(rB4.y - gB4.y) +
                        fabsf(rB4.z - gB4.z) + fabsf(rB4.w - gB4.w);

            acc_ce += (lseA - logitA) * wA + (lseB - logitB) * wB;
            acc_l1 += l1A * wA + l1B * wB;
            acc_w  += wA + wB;
        }
    }

    __shared__ float s_ce[8], s_l1[8], s_w[8];
    if (tx == 0) { s_ce[ty] = acc_ce; s_l1[ty] = acc_l1; s_w[ty] = acc_w; }
    __syncthreads();

    const int grp = (lvl * B + b) * 2 + gh;     // 0..95
    if (threadIdx.x == 0) {
        float a = 0.0f, c = 0.0f, nn = 0.0f;
#pragma unroll
        for (int i = 0; i < 8; i++) { a += s_ce[i]; c += s_l1[i]; nn += s_w[i]; }
        g_blk[0][grp] = a;
        g_blk[1][grp] = c;
        g_blk[2][grp] = nn;
        __threadfence();
        unsigned t = atomicAdd(&g_count, 1u);
        s_flag = (t == NGRP - 1);
    }
    __syncthreads();
    if (!s_flag) return;
    __threadfence();

    // ---------------- Phase C: final deterministic reduction --------------
    if (threadIdx.x < 32) {
        const int l = threadIdx.x;
        float a  = g_blk[0][l] + g_blk[0][l + 32] + g_blk[0][l + 64];
        float c  = g_blk[1][l] + g_blk[1][l + 32] + g_blk[1][l + 64];
        float nn = g_blk[2][l] + g_blk[2][l + 32] + g_blk[2][l + 64];
#pragma unroll
        for (int off = 16; off > 0; off >>= 1) {
            a  += __shfl_xor_sync(0xFFFFFFFFu, a, off);
            c  += __shfl_xor_sync(0xFFFFFFFFu, c, off);
            nn += __shfl_xor_sync(0xFFFFFFFFu, nn, off);
        }
        if (l == 0) {
            float denom = fmaxf(nn, 1.0f);
            out[0] = a / denom;
            out[1] = c / denom;
            out[2] = nn;
            g_count = 0;   // reset final ticket for next graph replay
        }
    }
}

// ---------------------------------------------------------------------------
// Bind inputs BY ELEMENT COUNT (metadata order is interleaved:
// cls_0, reg_0, cls_1, reg_1, cls_2, reg_2, gt, labels). All 8 element
// counts are distinct, so size-based binding is unambiguous.
// ---------------------------------------------------------------------------
extern "C" void kernel_launch(void* const* d_in, const int* in_sizes, int n_in,
                              void* d_out, int out_size) {
    const float* cls0 = 0; const float* cls1 = 0; const float* cls2 = 0;
    const float* reg0 = 0; const float* reg1 = 0; const float* reg2 = 0;
    const float* gt   = 0; const int*   lab  = 0;

    for (int i = 0; i < n_in; i++) {
        switch (in_sizes[i]) {
            case B * HW0 * NC: cls0 = (const float*)d_in[i]; break;  // 32,768,000
            case B * HW1 * NC: cls1 = (const float*)d_in[i]; break;  //  8,192,000
            case B * HW2 * NC: cls2 = (const float*)d_in[i]; break;  //  2,048,000
            case B * HW0 * 4:  reg0 = (const float*)d_in[i]; break;  //  1,638,400
            case B * HW1 * 4:  reg1 = (const float*)d_in[i]; break;  //    409,600
            case B * HW2 * 4:  reg2 = (const float*)d_in[i]; break;  //    102,400
            case B * N * 4:    gt   = (const float*)d_in[i]; break;  //      8,192
            case B * N:        lab  = (const int*)d_in[i];   break;  //      2,048
        }
    }

    dim3 grid(NCHUNKS, B, 2);
    fused_kernel<<<grid, 256>>>(cls0, cls1, cls2, reg0, reg1, reg2, gt, lab,
                                (float*)d_out);
}

// round 13
// speedup vs baseline: 1.1775x; 1.1775x over previous
#include <cuda_runtime.h>
#include <math.h>

#define B       16
#define N       128
#define NC      80
#define HW0     25600
#define HW1     6400
#define HW2     1600
#define CHUNK   800                  // MUST stay <= 1024 (10-bit local idx)
#define NITER   (CHUNK / 32)         // 25 pred iters per block
#define NTUP    (3 * B * N)          // 6144 tuples
#define CH0     (HW0 / CHUNK)        // 32
#define CH1     (HW1 / CHUNK)        // 8
#define CH2     (HW2 / CHUNK)        // 2
#define NCHUNKS (CH0 + CH1 + CH2)    // 42
#define GBLOCKS (NTUP / 16)          // 384 gather blocks (8 warps x 2 tuples)

// Scratch (no device allocations allowed).
// g_part transposed [B][N][chunk]: gather's 32-lane key load is contiguous.
__device__ unsigned long long g_part[B][N][NCHUNKS];
__device__ float        g_blk[3][GBLOCKS];            // per-block loss partials
__device__ unsigned int g_count;                      // last-block ticket (zero-init; reset each run)

// Packed f32x2 ops (sm_103a; ptxas won't auto-fuse -- must be PTX)
#define PACK_F32X2(out, lo, hi) \
    asm("mov.b64 %0, {%1, %2};" : "=l"(out) : "f"(lo), "f"(hi))
#define UNPACK_U32X2(lo, hi, in) \
    asm("mov.b64 {%0, %1}, %2;" : "=r"(lo), "=r"(hi) : "l"(in))
#define ADD_F32X2(out, a, b) \
    asm("add.rn.f32x2 %0, %1, %2;" : "=l"(out) : "l"(a), "l"(b))
#define MUL_F32X2(out, a, b) \
    asm("mul.rn.f32x2 %0, %1, %2;" : "=l"(out) : "l"(a), "l"(b))
#define FMA_F32X2(out, a, b, c) \
    asm("fma.rn.f32x2 %0, %1, %2, %3;" : "=l"(out) : "l"(a), "l"(b), "l"(c))

// ---------------------------------------------------------------------------
// Kernel 1: per-chunk nearest-pred search.
// R8 math/keys verbatim (bit-identical results), but:
//  - float2 pred loads (x,y only): half the bytes, half the L1tex wavefronts
//  - explicit 5-deep prefetch pipeline: 5 independent LDGs always in flight
// (R12's fused profile showed pipes ~25% busy, issue 41% -> latency-bound).
// Grid (NCHUNKS, B, 2). Block 256 = 32 lanes x 8 warps; 8 gts/thread.
//   key = (d2_bits & 0xFFFFFC00) | p_local   (LOP3)
//   kmin = umin(kmin, key)                   (IMNMX)
// ---------------------------------------------------------------------------
__global__ __launch_bounds__(256)
void argmin_kernel(const float* __restrict__ reg0,
                   const float* __restrict__ reg1,
                   const float* __restrict__ reg2,
                   const float* __restrict__ gt) {
    const int bx = blockIdx.x;   // chunk slot 0..41
    const int b  = blockIdx.y;
    const int gh = blockIdx.z;   // gt half

    int chunk, HW;
    const float* reg;
    if (bx < CH0)            { chunk = bx;               HW = HW0; reg = reg0; }
    else if (bx < CH0 + CH1) { chunk = bx - CH0;         HW = HW1; reg = reg1; }
    else                     { chunk = bx - (CH0 + CH1); HW = HW2; reg = reg2; }

    const int tx = threadIdx.x & 31;
    const int ty = threadIdx.x >> 5;           // 0..7
    const int gbase = gh * 64 + ty * 8;        // first of this thread's 8 gts

    // Pre-negated, packed gt coords: gnx[j] = (-gx[2j], -gx[2j+1])
    unsigned long long gnx[4], gny[4];
    unsigned kmin[8];
    const float* gtb = gt + ((size_t)b * N + gbase) * 4;
#pragma unroll
    for (int j = 0; j < 4; j++) {
        float a0 = -gtb[(2 * j    ) * 4 + 0];
        float a1 = -gtb[(2 * j + 1) * 4 + 0];
        float b0 = -gtb[(2 * j    ) * 4 + 1];
        float b1 = -gtb[(2 * j + 1) * 4 + 1];
        PACK_F32X2(gnx[j], a0, a1);
        PACK_F32X2(gny[j], b0, b1);
    }
#pragma unroll
    for (int i = 0; i < 8; i++) kmin[i] = 0xFFFFFFFFu;

    // float2 view: pred p's (x,y) is element 2*p (16B row stride, 8B aligned).
    const float2* regb2 = reinterpret_cast<const float2*>(reg + (size_t)b * HW * 4);
    const int pbase = chunk * CHUNK;

    // 5-deep prefetch pipeline over 25 iterations.
    float2 buf[5];
#pragma unroll
    for (int s = 0; s < 5; s++)
        buf[s] = regb2[(size_t)(pbase + s * 32 + tx) * 2];

#pragma unroll 5
    for (int it = 0; it < NITER - 5; it++) {
        float2 v = buf[it % 5];
        buf[it % 5] = regb2[(size_t)(pbase + (it + 5) * 32 + tx) * 2];
        const unsigned plocal = (unsigned)(it * 32) + (unsigned)tx;
        unsigned long long pxx, pyy;
        PACK_F32X2(pxx, v.x, v.x);
        PACK_F32X2(pyy, v.y, v.y);
#pragma unroll
        for (int j = 0; j < 4; j++) {
            unsigned long long dx2, dy2, m, d2v;
            ADD_F32X2(dx2, gnx[j], pxx);     // (px-gx, px-gx')
            ADD_F32X2(dy2, gny[j], pyy);
            MUL_F32X2(m, dx2, dx2);
            FMA_F32X2(d2v, dy2, dy2, m);
            unsigned lo, hi;
            UNPACK_U32X2(lo, hi, d2v);
            kmin[2 * j]     = umin(kmin[2 * j],     (lo & 0xFFFFFC00u) | plocal);
            kmin[2 * j + 1] = umin(kmin[2 * j + 1], (hi & 0xFFFFFC00u) | plocal);
        }
    }
#pragma unroll
    for (int it = NITER - 5; it < NITER; it++) {   // drain
        float2 v = buf[it % 5];
        const unsigned plocal = (unsigned)(it * 32) + (unsigned)tx;
        unsigned long long pxx, pyy;
        PACK_F32X2(pxx, v.x, v.x);
        PACK_F32X2(pyy, v.y, v.y);
#pragma unroll
        for (int j = 0; j < 4; j++) {
            unsigned long long dx2, dy2, m, d2v;
            ADD_F32X2(dx2, gnx[j], pxx);
            ADD_F32X2(dy2, gny[j], pyy);
            MUL_F32X2(m, dx2, dx2);
            FMA_F32X2(d2v, dy2, dy2, m);
            unsigned lo, hi;
            UNPACK_U32X2(lo, hi, d2v);
            kmin[2 * j]     = umin(kmin[2 * j],     (lo & 0xFFFFFC00u) | plocal);
            kmin[2 * j + 1] = umin(kmin[2 * j + 1], (hi & 0xFFFFFC00u) | plocal);
        }
    }

    // Warp reduce u32 keys; lane 0 writes u64 partial (trunc_d2, global idx).
#pragma unroll
    for (int i = 0; i < 8; i++) {
        unsigned k = kmin[i];
#pragma unroll
        for (int off = 16; off > 0; off >>= 1)
            k = umin(k, __shfl_xor_sync(0xFFFFFFFFu, k, off));
        if (tx == 0) {
            unsigned idx = (unsigned)pbase + (k & 0x3FFu);
            g_part[b][gbase + i][bx] =
                ((unsigned long long)(k & 0xFFFFFC00u) << 32) | idx;
        }
    }
}

// ---------------------------------------------------------------------------
// Kernel 2: fused gather + CE/L1 + full deterministic reduction (R11 form).
// TWO tuples per warp; 8 warps/block, 384 blocks. Scalar loads hoisted to
// overlap the logsumexp reductions. Exact d2 recomputed for the threshold.
// Last block (ticket) reduces all block partials and writes outputs.
// ---------------------------------------------------------------------------
__global__ __launch_bounds__(256)
void gather_kernel(const float* __restrict__ cls0,
                   const float* __restrict__ cls1,
                   const float* __restrict__ cls2,
                   const float* __restrict__ reg0,
                   const float* __restrict__ reg1,
                   const float* __restrict__ reg2,
                   const float* __restrict__ gt,
                   const int*   __restrict__ labels,
                   float*       __restrict__ out) {
    const int wib  = threadIdx.x >> 5;                  // warp in block 0..7
    const int lane = threadIdx.x & 31;
    const int w0   = (blockIdx.x * 8 + wib) * 2;        // first tuple id
    // w1 = w0 + 1 -- same level always (level boundary 2048 is even).

    const int lvl = w0 / (B * N);
    const int r0  = w0 - lvl * (B * N);
    const int r1  = r0 + 1;
    const int b0  = r0 / N, g0 = r0 - b0 * N;
    const int b1  = r1 / N, g1 = r1 - b1 * N;

    const float* cls; const float* reg; int HW, s0, nch;
    if (lvl == 0)      { cls = cls0; reg = reg0; HW = HW0; s0 = 0;         nch = CH0; }
    else if (lvl == 1) { cls = cls1; reg = reg1; HW = HW1; s0 = CH0;       nch = CH1; }
    else               { cls = cls2; reg = reg2; HW = HW2; s0 = CH0 + CH1; nch = CH2; }

    // Min over each tuple's chunk partials (contiguous in transposed g_part).
    unsigned long long keyA = 0xFFFFFFFFFFFFFFFFULL;
    unsigned long long keyB = 0xFFFFFFFFFFFFFFFFULL;
    if (lane < nch) {
        keyA = g_part[b0][g0][s0 + lane];
        keyB = g_part[b1][g1][s0 + lane];
    }
#pragma unroll
    for (int off = 16; off > 0; off >>= 1) {
        unsigned long long a2 = __shfl_xor_sync(0xFFFFFFFFu, keyA, off);
        unsigned long long b2 = __shfl_xor_sync(0xFFFFFFFFu, keyB, off);
        keyA = (a2 < keyA) ? a2 : keyA;
        keyB = (b2 < keyB) ? b2 : keyB;
    }
    const unsigned idA = (unsigned)keyA;
    const unsigned idB = (unsigned)keyB;

    // Issue ALL dependent scalar loads now; consume after the reductions.
    const float* crowA = cls + ((size_t)b0 * HW + idA) * NC;
    const float* crowB = cls + ((size_t)b1 * HW + idB) * NC;
    float4 gA = *reinterpret_cast<const float4*>(gt + ((size_t)b0 * N + g0) * 4);
    float4 gB = *reinterpret_cast<const float4*>(gt + ((size_t)b1 * N + g1) * 4);
    float4 rA = *reinterpret_cast<const float4*>(reg + ((size_t)b0 * HW + idA) * 4);
    float4 rB = *reinterpret_cast<const float4*>(reg + ((size_t)b1 * HW + idB) * 4);
    int labA = labels[b0 * N + g0];
    int labB = labels[b1 * N + g1];
    float logitA = crowA[labA];
    float logitB = crowB[labB];

    // CE via warp logsumexp over 80 classes, both tuples interleaved.
    const float NEGINF = -__int_as_float(0x7F800000);
    float a0 = NEGINF, a1 = NEGINF, a2v = NEGINF;
    float c0 = NEGINF, c1 = NEGINF, c2v = NEGINF;
    if (lane < NC)      { a0  = crowA[lane];      c0  = crowB[lane]; }
    if (lane + 32 < NC) { a1  = crowA[lane + 32]; c1  = crowB[lane + 32]; }
    if (lane + 64 < NC) { a2v = crowA[lane + 64]; c2v = crowB[lane + 64]; }
    float mxA = fmaxf(a0, fmaxf(a1, a2v));
    float mxB = fmaxf(c0, fmaxf(c1, c2v));
#pragma unroll
    for (int off = 16; off > 0; off >>= 1) {
        mxA = fmaxf(mxA, __shfl_xor_sync(0xFFFFFFFFu, mxA, off));
        mxB = fmaxf(mxB, __shfl_xor_sync(0xFFFFFFFFu, mxB, off));
    }
    float smA = 0.0f, smB = 0.0f;
    if (lane < NC)      { smA += expf(a0  - mxA); smB += expf(c0  - mxB); }
    if (lane + 32 < NC) { smA += expf(a1  - mxA); smB += expf(c1  - mxB); }
    if (lane + 64 < NC) { smA += expf(a2v - mxA); smB += expf(c2v - mxB); }
#pragma unroll
    for (int off = 16; off > 0; off >>= 1) {
        smA += __shfl_xor_sync(0xFFFFFFFFu, smA, off);
        smB += __shfl_xor_sync(0xFFFFFFFFu, smB, off);
    }
    float lseA = mxA + logf(smA);
    float lseB = mxB + logf(smB);

    __shared__ float s_ce[8], s_l1[8], s_w[8];
    __shared__ int   s_last;

    if (lane == 0) {
        float dxA = gA.x - rA.x, dyA = gA.y - rA.y;
        float dxB = gB.x - rB.x, dyB = gB.y - rB.y;
        float d2A = dxA * dxA + dyA * dyA;
        float d2B = dxB * dxB + dyB * dyB;
        float wA = (sqrtf(d2A) < 2.5f) ? 1.0f : 0.0f;
        float wB = (sqrtf(d2B) < 2.5f) ? 1.0f : 0.0f;

        float ceA = lseA - logitA;
        float ceB = lseB - logitB;
        float l1A = fabsf(rA.x - gA.x) + fabsf(rA.y - gA.y) +
                    fabsf(rA.z - gA.z) + fabsf(rA.w - gA.w);
        float l1B = fabsf(rB.x - gB.x) + fabsf(rB.y - gB.y) +
                    fabsf(rB.z - gB.z) + fabsf(rB.w - gB.w);

        s_ce[wib] = ceA * wA + ceB * wB;
        s_l1[wib] = l1A * wA + l1B * wB;
        s_w[wib]  = wA + wB;
    }
    __syncthreads();

    // Block partials + ticket
    if (threadIdx.x == 0) {
        float a = 0.0f, c = 0.0f, nn = 0.0f;
#pragma unroll
        for (int i = 0; i < 8; i++) { a += s_ce[i]; c += s_l1[i]; nn += s_w[i]; }
        g_blk[0][blockIdx.x] = a;
        g_blk[1][blockIdx.x] = c;
        g_blk[2][blockIdx.x] = nn;
        __threadfence();
        unsigned t = atomicAdd(&g_count, 1u);
        s_last = (t == GBLOCKS - 1);
    }
    __syncthreads();

    if (!s_last) return;

    // Last block: deterministic tree reduction of GBLOCKS partials.
    __shared__ float r0s[256], r1s[256], r2s[256];
    int tid = threadIdx.x;
    float a = 0.0f, c = 0.0f, nn = 0.0f;
    for (int i = tid; i < GBLOCKS; i += 256) {
        a  += g_blk[0][i];
        c  += g_blk[1][i];
        nn += g_blk[2][i];
    }
    r0s[tid] = a; r1s[tid] = c; r2s[tid] = nn;
    __syncthreads();
    for (int off = 128; off > 0; off >>= 1) {
        if (tid < off) {
            r0s[tid] += r0s[tid + off];
            r1s[tid] += r1s[tid + off];
            r2s[tid] += r2s[tid + off];
        }
        __syncthreads();
    }
    if (tid == 0) {
        float np    = r2s[0];
        float denom = fmaxf(np, 1.0f);
        out[0] = r0s[0] / denom;
        out[1] = r1s[0] / denom;
        out[2] = np;
        g_count = 0;   // reset ticket for next graph replay
    }
}

// ---------------------------------------------------------------------------
// Bind inputs BY ELEMENT COUNT (metadata order is interleaved:
// cls_0, reg_0, cls_1, reg_1, cls_2, reg_2, gt, labels). All 8 element
// counts are distinct, so size-based binding is unambiguous.
// ---------------------------------------------------------------------------
extern "C" void kernel_launch(void* const* d_in, const int* in_sizes, int n_in,
                              void* d_out, int out_size) {
    const float* cls0 = 0; const float* cls1 = 0; const float* cls2 = 0;
    const float* reg0 = 0; const float* reg1 = 0; const float* reg2 = 0;
    const float* gt   = 0; const int*   lab  = 0;

    for (int i = 0; i < n_in; i++) {
        switch (in_sizes[i]) {
            case B * HW0 * NC: cls0 = (const float*)d_in[i]; break;  // 32,768,000
            case B * HW1 * NC: cls1 = (const float*)d_in[i]; break;  //  8,192,000
            case B * HW2 * NC: cls2 = (const float*)d_in[i]; break;  //  2,048,000
            case B * HW0 * 4:  reg0 = (const float*)d_in[i]; break;  //  1,638,400
            case B * HW1 * 4:  reg1 = (const float*)d_in[i]; break;  //    409,600
            case B * HW2 * 4:  reg2 = (const float*)d_in[i]; break;  //    102,400
            case B * N * 4:    gt   = (const float*)d_in[i]; break;  //      8,192
            case B * N:        lab  = (const int*)d_in[i];   break;  //      2,048
        }
    }

    dim3 grid(NCHUNKS, B, 2);
    argmin_kernel<<<grid, 256>>>(reg0, reg1, reg2, gt);

    gather_kernel<<<GBLOCKS, 256>>>(cls0, cls1, cls2, reg0, reg1, reg2, gt, lab,
                                    (float*)d_out);
}